// round 3
// baseline (speedup 1.0000x reference)
#include <cuda_runtime.h>

#define TT 25
#define BB 4096
#define INP 500
#define HH 64
#define GG 256   // 4*H
#define NL 25
#define RPB 32       // batch rows per block
#define NTHR 256

typedef unsigned long long ull;

// scratch (sanctioned: __device__ globals)
// g_xp0 stored in packed-pair layout: [row][p*32+lane] = (gate lane+64p, gate lane+64p+32)
__device__ ull   g_xp0[(size_t)TT * BB * 128];
__device__ float g_hs[2][(size_t)TT * BB * HH];

__device__ __forceinline__ ull ffma2(ull a, ull b, ull c) {
    ull d;
    asm("fma.rn.f32x2 %0, %1, %2, %3;" : "=l"(d) : "l"(a), "l"(b), "l"(c));
    return d;
}
__device__ __forceinline__ ull pack2(float x, float y) {
    ull d;
    asm("mov.b64 %0, {%1, %2};" : "=l"(d) : "f"(x), "f"(y));
    return d;
}
__device__ __forceinline__ float2 unpack2(ull v) {
    float2 r;
    asm("mov.b64 {%0, %1}, %2;" : "=f"(r.x), "=f"(r.y) : "l"(v));
    return r;
}
__device__ __forceinline__ float sigf(float x) {
    return __fdividef(1.0f, 1.0f + __expf(-x));
}
__device__ __forceinline__ float tanhf_fast(float x) {
    return 1.0f - __fdividef(2.0f, __expf(2.0f * x) + 1.0f);
}

// shared weight layout: ull slot [(k*4+p)*32 + lane] = (W[lane+64p][k], W[lane+64p+32][k])
// staging (float view): fidx = ((k*4+p)*32 + (g&31))*2 + ((g>>5)&1),  p = g>>6

// ---------------------------------------------------------------------------
// Layer-0 input projection -> g_xp0 (packed pairs), bias folded in
// ---------------------------------------------------------------------------
__global__ void __launch_bounds__(NTHR)
proj0_kernel(const float* __restrict__ x, const float* __restrict__ W,
             const float* __restrict__ bih, const float* __restrict__ bhh)
{
    extern __shared__ unsigned char smraw[];
    ull*   shW  = (ull*)smraw;                 // 64*4*32 ull = 64 KB
    float* shWf = (float*)shW;
    float* shX  = (float*)(smraw + 65536);     // [32][64]
    const int tid = threadIdx.x, lane = tid & 31, w = tid >> 5;
    const int rowBase = blockIdx.x * RPB;

    ull acc[4][4];
#pragma unroll
    for (int p = 0; p < 4; ++p) {
        int g0 = lane + 64 * p, g1 = g0 + 32;
        ull b = pack2(bih[g0] + bhh[g0], bih[g1] + bhh[g1]);
#pragma unroll
        for (int r = 0; r < 4; ++r) acc[r][p] = b;
    }

    for (int k0 = 0; k0 < INP; k0 += 64) {
        for (int idx = tid; idx < 64 * GG; idx += NTHR) {
            int kk = idx & 63, g = idx >> 6;
            float v = (k0 + kk < INP) ? W[(size_t)g * INP + k0 + kk] : 0.0f;
            int p = g >> 6, half = (g >> 5) & 1, l2 = g & 31;
            shWf[((kk * 4 + p) * 32 + l2) * 2 + half] = v;
        }
        for (int idx = tid; idx < RPB * 64; idx += NTHR) {
            int kk = idx & 63, r = idx >> 6;
            shX[r * 64 + kk] = (k0 + kk < INP) ? x[(size_t)(rowBase + r) * INP + k0 + kk] : 0.0f;
        }
        __syncthreads();
#pragma unroll 4
        for (int k4 = 0; k4 < 64; k4 += 4) {
            float4 xq[4];
#pragma unroll
            for (int r = 0; r < 4; ++r) xq[r] = *(const float4*)&shX[(4 * w + r) * 64 + k4];
#pragma unroll
            for (int kk = 0; kk < 4; ++kk) {
                ull wv[4];
#pragma unroll
                for (int p = 0; p < 4; ++p) wv[p] = shW[((k4 + kk) * 4 + p) * 32 + lane];
#pragma unroll
                for (int r = 0; r < 4; ++r) {
                    float xv = ((const float*)&xq[r])[kk];
                    ull xx = pack2(xv, xv);
#pragma unroll
                    for (int p = 0; p < 4; ++p) acc[r][p] = ffma2(xx, wv[p], acc[r][p]);
                }
            }
        }
        __syncthreads();
    }
#pragma unroll
    for (int r = 0; r < 4; ++r) {
        size_t rb = (size_t)(rowBase + 4 * w + r) * 128;
#pragma unroll
        for (int p = 0; p < 4; ++p) g_xp0[rb + p * 32 + lane] = acc[r][p];
    }
}

// ---------------------------------------------------------------------------
// Layer 0 recurrence (K=64): gates = xp0[t] + h @ Whh^T
// ---------------------------------------------------------------------------
__global__ void __launch_bounds__(NTHR)
layer0_kernel(const float* __restrict__ Whh,
              float* __restrict__ out_hn, float* __restrict__ out_cn)
{
    extern __shared__ unsigned char smraw[];
    ull*   shW  = (ull*)smraw;                 // 64*4*32 ull
    float* shWf = (float*)shW;
    float* shH  = (float*)(smraw + 65536);     // [32][64]
    const int tid = threadIdx.x, lane = tid & 31, w = tid >> 5;
    const int rowBase = blockIdx.x * RPB;

    for (int idx = tid; idx < 64 * GG; idx += NTHR) {
        int kk = idx & 63, g = idx >> 6;
        int p = g >> 6, half = (g >> 5) & 1, l2 = g & 31;
        shWf[((kk * 4 + p) * 32 + l2) * 2 + half] = Whh[g * HH + kk];
    }
    for (int idx = tid; idx < RPB * HH; idx += NTHR) shH[idx] = 0.0f;
    __syncthreads();

    float c0[4] = {0, 0, 0, 0}, c1[4] = {0, 0, 0, 0};

    for (int t = 0; t < TT; ++t) {
        ull acc[4][4];
#pragma unroll
        for (int r = 0; r < 4; ++r) {
            size_t base = ((size_t)t * BB + rowBase + 4 * w + r) * 128;
#pragma unroll
            for (int p = 0; p < 4; ++p) acc[r][p] = g_xp0[base + p * 32 + lane];
        }
#pragma unroll 4
        for (int k4 = 0; k4 < 64; k4 += 4) {
            float4 xq[4];
#pragma unroll
            for (int r = 0; r < 4; ++r) xq[r] = *(const float4*)&shH[(4 * w + r) * 64 + k4];
#pragma unroll
            for (int kk = 0; kk < 4; ++kk) {
                ull wv[4];
#pragma unroll
                for (int p = 0; p < 4; ++p) wv[p] = shW[((k4 + kk) * 4 + p) * 32 + lane];
#pragma unroll
                for (int r = 0; r < 4; ++r) {
                    float xv = ((const float*)&xq[r])[kk];
                    ull xx = pack2(xv, xv);
#pragma unroll
                    for (int p = 0; p < 4; ++p) acc[r][p] = ffma2(xx, wv[p], acc[r][p]);
                }
            }
        }
        __syncwarp();
#pragma unroll
        for (int r = 0; r < 4; ++r) {
            float2 fi = unpack2(acc[r][0]), ff = unpack2(acc[r][1]);
            float2 fq = unpack2(acc[r][2]), fo = unpack2(acc[r][3]);
            float i0 = sigf(fi.x), i1 = sigf(fi.y);
            float f0 = sigf(ff.x), f1 = sigf(ff.y);
            float q0 = tanhf_fast(fq.x), q1 = tanhf_fast(fq.y);
            float o0 = sigf(fo.x), o1 = sigf(fo.y);
            c0[r] = f0 * c0[r] + i0 * q0;
            c1[r] = f1 * c1[r] + i1 * q1;
            float h0 = o0 * tanhf_fast(c0[r]);
            float h1 = o1 * tanhf_fast(c1[r]);
            shH[(4 * w + r) * 64 + lane]      = h0;
            shH[(4 * w + r) * 64 + lane + 32] = h1;
            size_t ob = ((size_t)t * BB + rowBase + 4 * w + r) * HH;
            g_hs[0][ob + lane]      = h0;
            g_hs[0][ob + lane + 32] = h1;
            if (t == TT - 1) {
                size_t hb = (size_t)(rowBase + 4 * w + r) * HH;
                out_hn[hb + lane] = h0;      out_hn[hb + lane + 32] = h1;
                out_cn[hb + lane] = c0[r];   out_cn[hb + lane + 32] = c1[r];
            }
        }
        __syncwarp();
    }
}

// ---------------------------------------------------------------------------
// Hidden layer l>=1 (fused K=128): gates = bias + x_in @ Wih^T + h @ Whh^T
// ---------------------------------------------------------------------------
__global__ void __launch_bounds__(NTHR)
layer_kernel(const float* __restrict__ Wih, const float* __restrict__ Whh,
             const float* __restrict__ bih, const float* __restrict__ bhh,
             int inSel, int outSel,
             float* __restrict__ out_hn, float* __restrict__ out_cn)
{
    extern __shared__ unsigned char smraw[];
    ull*   shW  = (ull*)smraw;                  // 128*4*32 ull = 128 KB
    float* shWf = (float*)shW;
    float* shXH = (float*)(smraw + 131072);     // [32][128]: 0..63 x_in, 64..127 h
    const int tid = threadIdx.x, lane = tid & 31, w = tid >> 5;
    const int rowBase = blockIdx.x * RPB;
    const float* __restrict__ hs_in  = g_hs[inSel];
    float* __restrict__       hs_out = g_hs[outSel];

    for (int idx = tid; idx < 64 * GG; idx += NTHR) {
        int kk = idx & 63, g = idx >> 6;
        int p = g >> 6, half = (g >> 5) & 1, l2 = g & 31;
        shWf[((kk * 4 + p) * 32 + l2) * 2 + half]        = Wih[g * HH + kk];
        shWf[(((64 + kk) * 4 + p) * 32 + l2) * 2 + half] = Whh[g * HH + kk];
    }
    for (int idx = tid; idx < RPB * HH; idx += NTHR) {
        int r = idx >> 6, k = idx & 63;
        shXH[r * 128 + 64 + k] = 0.0f;
    }
    ull bsum[4];
#pragma unroll
    for (int p = 0; p < 4; ++p) {
        int g0 = lane + 64 * p, g1 = g0 + 32;
        bsum[p] = pack2(bih[g0] + bhh[g0], bih[g1] + bhh[g1]);
    }
    __syncthreads();

    float c0[4] = {0, 0, 0, 0}, c1[4] = {0, 0, 0, 0};
    const int lr = lane >> 3;          // which of my warp's rows I help stage
    const int kb = (lane & 7) * 8;     // k offset

    for (int t = 0; t < TT; ++t) {
        {   // per-warp staging of x_in for this warp's 4 rows
            size_t gb = ((size_t)t * BB + rowBase + 4 * w + lr) * HH + kb;
            float4 a = *(const float4*)&hs_in[gb];
            float4 b = *(const float4*)&hs_in[gb + 4];
            float* dst = &shXH[(4 * w + lr) * 128 + kb];
            *(float4*)dst       = a;
            *(float4*)(dst + 4) = b;
        }
        __syncwarp();

        ull acc[4][4];
#pragma unroll
        for (int r = 0; r < 4; ++r)
#pragma unroll
            for (int p = 0; p < 4; ++p) acc[r][p] = bsum[p];

#pragma unroll 4
        for (int k4 = 0; k4 < 128; k4 += 4) {
            float4 xq[4];
#pragma unroll
            for (int r = 0; r < 4; ++r) xq[r] = *(const float4*)&shXH[(4 * w + r) * 128 + k4];
#pragma unroll
            for (int kk = 0; kk < 4; ++kk) {
                ull wv[4];
#pragma unroll
                for (int p = 0; p < 4; ++p) wv[p] = shW[((k4 + kk) * 4 + p) * 32 + lane];
#pragma unroll
                for (int r = 0; r < 4; ++r) {
                    float xv = ((const float*)&xq[r])[kk];
                    ull xx = pack2(xv, xv);
#pragma unroll
                    for (int p = 0; p < 4; ++p) acc[r][p] = ffma2(xx, wv[p], acc[r][p]);
                }
            }
        }
        __syncwarp();
#pragma unroll
        for (int r = 0; r < 4; ++r) {
            float2 fi = unpack2(acc[r][0]), ff = unpack2(acc[r][1]);
            float2 fq = unpack2(acc[r][2]), fo = unpack2(acc[r][3]);
            float i0 = sigf(fi.x), i1 = sigf(fi.y);
            float f0 = sigf(ff.x), f1 = sigf(ff.y);
            float q0 = tanhf_fast(fq.x), q1 = tanhf_fast(fq.y);
            float o0 = sigf(fo.x), o1 = sigf(fo.y);
            c0[r] = f0 * c0[r] + i0 * q0;
            c1[r] = f1 * c1[r] + i1 * q1;
            float h0 = o0 * tanhf_fast(c0[r]);
            float h1 = o1 * tanhf_fast(c1[r]);
            shXH[(4 * w + r) * 128 + 64 + lane]      = h0;
            shXH[(4 * w + r) * 128 + 64 + lane + 32] = h1;
            size_t ob = ((size_t)t * BB + rowBase + 4 * w + r) * HH;
            hs_out[ob + lane]      = h0;
            hs_out[ob + lane + 32] = h1;
            if (t == TT - 1) {
                size_t hb = (size_t)(rowBase + 4 * w + r) * HH;
                out_hn[hb + lane] = h0;      out_hn[hb + lane + 32] = h1;
                out_cn[hb + lane] = c0[r];   out_cn[hb + lane + 32] = c1[r];
            }
        }
        __syncwarp();
    }
}

// ---------------------------------------------------------------------------
// Final linear on hs[:, -1, :] (batch index B-1, faithful to reference quirk)
// ---------------------------------------------------------------------------
__global__ void final_kernel(const float* __restrict__ Wlin,
                             const float* __restrict__ blin,
                             float* __restrict__ out)
{
    int idx = threadIdx.x;
    if (idx < TT * 10) {
        int t = idx / 10, o = idx % 10;
        const float* h = &g_hs[0][((size_t)t * BB + (BB - 1)) * HH];
        float s = blin[o];
#pragma unroll
        for (int k = 0; k < HH; ++k) s += h[k] * Wlin[o * HH + k];
        out[idx] = s;
    }
}

// ---------------------------------------------------------------------------
extern "C" void kernel_launch(void* const* d_in, const int* in_sizes, int n_in,
                              void* d_out, int out_size)
{
    const float* x    = (const float*)d_in[0];
    const float* Wih0 = (const float*)d_in[1];
    const float* Whh0 = (const float*)d_in[2];
    const float* bih0 = (const float*)d_in[3];
    const float* bhh0 = (const float*)d_in[4];
    const float* WihR = (const float*)d_in[5];
    const float* WhhR = (const float*)d_in[6];
    const float* bihR = (const float*)d_in[7];
    const float* bhhR = (const float*)d_in[8];
    const float* Wlin = (const float*)d_in[9];
    const float* blin = (const float*)d_in[10];

    float* out = (float*)d_out;
    float* hn  = out + TT * 10;
    float* cn  = hn + (size_t)NL * BB * HH;

    const int SH_P  = 65536 + RPB * 64 * 4;           // 73728 B
    const int SH_L0 = 65536 + RPB * 64 * 4;           // 73728 B
    const int SH_HL = 131072 + RPB * 128 * 4;         // 147456 B

    cudaFuncSetAttribute(proj0_kernel,  cudaFuncAttributeMaxDynamicSharedMemorySize, SH_P);
    cudaFuncSetAttribute(layer0_kernel, cudaFuncAttributeMaxDynamicSharedMemorySize, SH_L0);
    cudaFuncSetAttribute(layer_kernel,  cudaFuncAttributeMaxDynamicSharedMemorySize, SH_HL);

    proj0_kernel<<<(TT * BB) / RPB, NTHR, SH_P>>>(x, Wih0, bih0, bhh0);
    layer0_kernel<<<BB / RPB, NTHR, SH_L0>>>(Whh0, hn, cn);

    for (int l = 1; l < NL; ++l) {
        int lr = l - 1;
        layer_kernel<<<BB / RPB, NTHR, SH_HL>>>(
            WihR + (size_t)lr * GG * HH, WhhR + (size_t)lr * GG * HH,
            bihR + lr * GG, bhhR + lr * GG,
            (l - 1) & 1, l & 1,
            hn + (size_t)l * BB * HH, cn + (size_t)l * BB * HH);
    }

    final_kernel<<<1, 256>>>(Wlin, blin, out);
}

// round 6
// speedup vs baseline: 1.2046x; 1.2046x over previous
#include <cuda_runtime.h>

#define TT 25
#define BB 4096
#define INP 500
#define HH 64
#define GG 256   // 4*H
#define NL 25
#define NTHR 256

typedef unsigned long long ull;

// scratch (sanctioned: __device__ globals)
// g_xp0 packed-pair layout: [row][p*32+lane] = (gate lane+64p, gate lane+64p+32)
__device__ ull   g_xp0[(size_t)TT * BB * 128];
__device__ float g_hs[2][(size_t)TT * BB * HH];

__device__ __forceinline__ ull ffma2(ull a, ull b, ull c) {
    ull d; asm("fma.rn.f32x2 %0, %1, %2, %3;" : "=l"(d) : "l"(a), "l"(b), "l"(c)); return d;
}
__device__ __forceinline__ ull add2(ull a, ull b) {
    ull d; asm("add.rn.f32x2 %0, %1, %2;" : "=l"(d) : "l"(a), "l"(b)); return d;
}
__device__ __forceinline__ ull pack2(float x, float y) {
    ull d; asm("mov.b64 %0, {%1, %2};" : "=l"(d) : "f"(x), "f"(y)); return d;
}
__device__ __forceinline__ float2 unpack2(ull v) {
    float2 r; asm("mov.b64 {%0, %1}, %2;" : "=f"(r.x), "=f"(r.y) : "l"(v)); return r;
}
__device__ __forceinline__ float sigf(float x) {
    return __fdividef(1.0f, 1.0f + __expf(-x));
}
__device__ __forceinline__ float tanhf_fast(float x) {
    return 1.0f - __fdividef(2.0f, __expf(2.0f * x) + 1.0f);
}

// shared weight layout (ull): slot [(k*4+p)*32 + lane] = (W[lane+64p][k], W[lane+64p+32][k])

// ---------------------------------------------------------------------------
// Layer-0 input projection -> g_xp0 (packed pairs), bias folded in.
// 64 rows/block, 8 warps x 8 rows. Conflict-free staging via padded scratch.
// ---------------------------------------------------------------------------
#define RPP 64
__global__ void __launch_bounds__(NTHR)
proj0_kernel(const float* __restrict__ x, const float* __restrict__ W,
             const float* __restrict__ bih, const float* __restrict__ bhh)
{
    extern __shared__ unsigned char smraw[];
    ull*   shW     = (ull*)smraw;                        // 64*4*32 ull = 64 KB
    float* scratch = (float*)(smraw + 65536);            // [256][65] = 66560 B
    float* shX     = (float*)(smraw + 65536 + 66560);    // [64][64]  = 16 KB
    const int tid = threadIdx.x, lane = tid & 31, w = tid >> 5;
    const int rowBase = blockIdx.x * RPP;

    ull acc[8][4];
#pragma unroll
    for (int p = 0; p < 4; ++p) {
        int g0 = lane + 64 * p, g1 = g0 + 32;
        ull b = pack2(bih[g0] + bhh[g0], bih[g1] + bhh[g1]);
#pragma unroll
        for (int r = 0; r < 8; ++r) acc[r][p] = b;
    }

    for (int k0 = 0; k0 < INP; k0 += 64) {
        // pass 1: coalesced global -> linear scratch (pad 65), plus x tile
        for (int idx = tid; idx < 64 * GG; idx += NTHR) {
            int kk = idx & 63, g = idx >> 6;
            scratch[g * 65 + kk] = (k0 + kk < INP) ? W[(size_t)g * INP + k0 + kk] : 0.0f;
        }
        for (int idx = tid; idx < RPP * 64; idx += NTHR) {
            int kk = idx & 63, r = idx >> 6;
            shX[r * 64 + kk] = (k0 + kk < INP) ? x[(size_t)(rowBase + r) * INP + k0 + kk] : 0.0f;
        }
        __syncthreads();
        // pass 2: repack scratch -> shW (conflict-free: stride-65 reads, linear ull writes)
        for (int idx = tid; idx < 64 * 128; idx += NTHR) {
            int l2 = idx & 31, p = (idx >> 5) & 3, kk = idx >> 7;
            int g0 = 64 * p + l2;
            shW[(kk * 4 + p) * 32 + l2] = pack2(scratch[g0 * 65 + kk], scratch[(g0 + 32) * 65 + kk]);
        }
        __syncthreads();
#pragma unroll 2
        for (int k4 = 0; k4 < 64; k4 += 4) {
            float4 xq[8];
#pragma unroll
            for (int r = 0; r < 8; ++r) xq[r] = *(const float4*)&shX[(8 * w + r) * 64 + k4];
#pragma unroll
            for (int kk = 0; kk < 4; ++kk) {
                ull wv[4];
#pragma unroll
                for (int p = 0; p < 4; ++p) wv[p] = shW[((k4 + kk) * 4 + p) * 32 + lane];
#pragma unroll
                for (int r = 0; r < 8; ++r) {
                    float xv = ((const float*)&xq[r])[kk];
                    ull xx = pack2(xv, xv);
#pragma unroll
                    for (int p = 0; p < 4; ++p) acc[r][p] = ffma2(xx, wv[p], acc[r][p]);
                }
            }
        }
        __syncthreads();
    }
#pragma unroll
    for (int r = 0; r < 8; ++r) {
        size_t rb = (size_t)(rowBase + 8 * w + r) * 128;
#pragma unroll
        for (int p = 0; p < 4; ++p) g_xp0[rb + p * 32 + lane] = acc[r][p];
    }
}

// ---------------------------------------------------------------------------
// Layer 0 recurrence (K=64): gates = xp0[t] + h @ Whh^T. 32 rows/block.
// ---------------------------------------------------------------------------
__global__ void __launch_bounds__(NTHR)
layer0_kernel(const float* __restrict__ Whh,
              float* __restrict__ out_hn, float* __restrict__ out_cn)
{
    extern __shared__ unsigned char smraw[];
    ull*   shW  = (ull*)smraw;                 // 64*4*32 ull
    float* shWf = (float*)shW;
    float* shH  = (float*)(smraw + 65536);     // [32][64]
    const int tid = threadIdx.x, lane = tid & 31, w = tid >> 5;
    const int rowBase = blockIdx.x * 32;

    // g-fast staging: only 2-way STS conflicts
    for (int idx = tid; idx < 64 * GG; idx += NTHR) {
        int g = idx & 255, kk = idx >> 8;
        int p = g >> 6, half = (g >> 5) & 1, l2 = g & 31;
        shWf[((kk * 4 + p) * 32 + l2) * 2 + half] = Whh[g * HH + kk];
    }
    for (int idx = tid; idx < 32 * HH; idx += NTHR) shH[idx] = 0.0f;
    __syncthreads();

    float c0[4] = {0, 0, 0, 0}, c1[4] = {0, 0, 0, 0};

    for (int t = 0; t < TT; ++t) {
        ull acc[4][4];
#pragma unroll
        for (int r = 0; r < 4; ++r) {
            size_t base = ((size_t)t * BB + rowBase + 4 * w + r) * 128;
#pragma unroll
            for (int p = 0; p < 4; ++p) acc[r][p] = g_xp0[base + p * 32 + lane];
        }
#pragma unroll 4
        for (int k4 = 0; k4 < 64; k4 += 4) {
            float4 xq[4];
#pragma unroll
            for (int r = 0; r < 4; ++r) xq[r] = *(const float4*)&shH[(4 * w + r) * 64 + k4];
#pragma unroll
            for (int kk = 0; kk < 4; ++kk) {
                ull wv[4];
#pragma unroll
                for (int p = 0; p < 4; ++p) wv[p] = shW[((k4 + kk) * 4 + p) * 32 + lane];
#pragma unroll
                for (int r = 0; r < 4; ++r) {
                    float xv = ((const float*)&xq[r])[kk];
                    ull xx = pack2(xv, xv);
#pragma unroll
                    for (int p = 0; p < 4; ++p) acc[r][p] = ffma2(xx, wv[p], acc[r][p]);
                }
            }
        }
        __syncwarp();
#pragma unroll
        for (int r = 0; r < 4; ++r) {
            float2 fi = unpack2(acc[r][0]), ff = unpack2(acc[r][1]);
            float2 fq = unpack2(acc[r][2]), fo = unpack2(acc[r][3]);
            float i0 = sigf(fi.x), i1 = sigf(fi.y);
            float f0 = sigf(ff.x), f1 = sigf(ff.y);
            float q0 = tanhf_fast(fq.x), q1 = tanhf_fast(fq.y);
            float o0 = sigf(fo.x), o1 = sigf(fo.y);
            c0[r] = f0 * c0[r] + i0 * q0;
            c1[r] = f1 * c1[r] + i1 * q1;
            float h0 = o0 * tanhf_fast(c0[r]);
            float h1 = o1 * tanhf_fast(c1[r]);
            shH[(4 * w + r) * 64 + lane]      = h0;
            shH[(4 * w + r) * 64 + lane + 32] = h1;
            size_t ob = ((size_t)t * BB + rowBase + 4 * w + r) * HH;
            g_hs[0][ob + lane]      = h0;
            g_hs[0][ob + lane + 32] = h1;
            if (t == TT - 1) {
                size_t hb = (size_t)(rowBase + 4 * w + r) * HH;
                out_hn[hb + lane] = h0;      out_hn[hb + lane + 32] = h1;
                out_cn[hb + lane] = c0[r];   out_cn[hb + lane + 32] = c1[r];
            }
        }
        __syncwarp();
    }
}

// ---------------------------------------------------------------------------
// Hidden layer l>=1 (fused K=128), 512 threads / 16 warps:
//   warps 0-7  (wg=0): k 0..63  (x part) + reduction + elementwise
//   warps 8-15 (wg=1): k 64..127 (h part) + next-t x prefetch
// ---------------------------------------------------------------------------
__global__ void __launch_bounds__(512)
layer_kernel(const float* __restrict__ Wih, const float* __restrict__ Whh,
             const float* __restrict__ bih, const float* __restrict__ bhh,
             int inSel, int outSel,
             float* __restrict__ out_hn, float* __restrict__ out_cn)
{
    extern __shared__ unsigned char smraw[];
    ull*   shW  = (ull*)smraw;                  // 128*4*32 ull = 128 KB
    float* shWf = (float*)shW;
    float* shXH = (float*)(smraw + 131072);     // [32][128]: 0..63 x_in, 64..127 h
    ull*   red  = (ull*)(smraw + 131072 + 16384); // [8 rg][4 r][4 p][32 lane] = 32 KB
    const int tid = threadIdx.x, lane = tid & 31, w = tid >> 5;
    const int wg = w >> 3, rg = w & 7;
    const int rowBase = blockIdx.x * 32;
    const float* __restrict__ hs_in  = g_hs[inSel];
    float* __restrict__       hs_out = g_hs[outSel];

    // stage both weight halves, g-fast (2-way STS conflict only)
    for (int idx = tid; idx < 64 * GG; idx += 512) {
        int g = idx & 255, kk = idx >> 8;
        int p = g >> 6, half = (g >> 5) & 1, l2 = g & 31;
        shWf[((kk * 4 + p) * 32 + l2) * 2 + half]        = Wih[g * HH + kk];
        shWf[(((64 + kk) * 4 + p) * 32 + l2) * 2 + half] = Whh[g * HH + kk];
    }
    for (int idx = tid; idx < 32 * HH; idx += 512) {
        int r = idx >> 6, k = idx & 63;
        shXH[r * 128 + 64 + k] = 0.0f;
    }
    ull bsum[4];
#pragma unroll
    for (int p = 0; p < 4; ++p) {
        int g0 = lane + 64 * p, g1 = g0 + 32;
        bsum[p] = pack2(bih[g0] + bhh[g0], bih[g1] + bhh[g1]);
    }

    const int lr = lane >> 3;          // row-within-group I help stage
    const int kb = (lane & 7) * 8;     // k offset
    // pre-stage x(t=0) by wg=1 warps
    if (wg == 1) {
        size_t gb = ((size_t)0 * BB + rowBase + 4 * rg + lr) * HH + kb;
        float4 a = *(const float4*)&hs_in[gb];
        float4 b = *(const float4*)&hs_in[gb + 4];
        float* dst = &shXH[(4 * rg + lr) * 128 + kb];
        *(float4*)dst = a; *(float4*)(dst + 4) = b;
    }
    __syncthreads();

    float c0[4] = {0, 0, 0, 0}, c1[4] = {0, 0, 0, 0};
    const int kbase = wg * 64;

    for (int t = 0; t < TT; ++t) {
        ull acc[4][4];
#pragma unroll
        for (int r = 0; r < 4; ++r)
#pragma unroll
            for (int p = 0; p < 4; ++p) acc[r][p] = (wg == 0) ? bsum[p] : 0ULL;

#pragma unroll 4
        for (int k4 = 0; k4 < 64; k4 += 4) {
            float4 xq[4];
#pragma unroll
            for (int r = 0; r < 4; ++r)
                xq[r] = *(const float4*)&shXH[(4 * rg + r) * 128 + kbase + k4];
#pragma unroll
            for (int kk = 0; kk < 4; ++kk) {
                ull wv[4];
#pragma unroll
                for (int p = 0; p < 4; ++p) wv[p] = shW[((kbase + k4 + kk) * 4 + p) * 32 + lane];
#pragma unroll
                for (int r = 0; r < 4; ++r) {
                    float xv = ((const float*)&xq[r])[kk];
                    ull xx = pack2(xv, xv);
#pragma unroll
                    for (int p = 0; p < 4; ++p) acc[r][p] = ffma2(xx, wv[p], acc[r][p]);
                }
            }
        }
        if (wg == 1) {
#pragma unroll
            for (int r = 0; r < 4; ++r)
#pragma unroll
                for (int p = 0; p < 4; ++p)
                    red[((rg * 4 + r) * 4 + p) * 32 + lane] = acc[r][p];
        }
        __syncthreads();
        if (wg == 0) {
#pragma unroll
            for (int r = 0; r < 4; ++r) {
#pragma unroll
                for (int p = 0; p < 4; ++p)
                    acc[r][p] = add2(acc[r][p], red[((rg * 4 + r) * 4 + p) * 32 + lane]);
                float2 fi = unpack2(acc[r][0]), ff = unpack2(acc[r][1]);
                float2 fq = unpack2(acc[r][2]), fo = unpack2(acc[r][3]);
                float i0 = sigf(fi.x), i1 = sigf(fi.y);
                float f0 = sigf(ff.x), f1 = sigf(ff.y);
                float q0 = tanhf_fast(fq.x), q1 = tanhf_fast(fq.y);
                float o0 = sigf(fo.x), o1 = sigf(fo.y);
                c0[r] = f0 * c0[r] + i0 * q0;
                c1[r] = f1 * c1[r] + i1 * q1;
                float h0 = o0 * tanhf_fast(c0[r]);
                float h1 = o1 * tanhf_fast(c1[r]);
                shXH[(4 * rg + r) * 128 + 64 + lane]      = h0;
                shXH[(4 * rg + r) * 128 + 64 + lane + 32] = h1;
                size_t ob = ((size_t)t * BB + rowBase + 4 * rg + r) * HH;
                hs_out[ob + lane]      = h0;
                hs_out[ob + lane + 32] = h1;
                if (t == TT - 1) {
                    size_t hb = (size_t)(rowBase + 4 * rg + r) * HH;
                    out_hn[hb + lane] = h0;      out_hn[hb + lane + 32] = h1;
                    out_cn[hb + lane] = c0[r];   out_cn[hb + lane + 32] = c1[r];
                }
            }
        } else if (t + 1 < TT) {
            // prefetch next-t x while wg0 does elementwise
            size_t gb = ((size_t)(t + 1) * BB + rowBase + 4 * rg + lr) * HH + kb;
            float4 a = *(const float4*)&hs_in[gb];
            float4 b = *(const float4*)&hs_in[gb + 4];
            float* dst = &shXH[(4 * rg + lr) * 128 + kb];
            *(float4*)dst = a; *(float4*)(dst + 4) = b;
        }
        __syncthreads();
    }
}

// ---------------------------------------------------------------------------
// Final linear on hs[:, -1, :] (batch index B-1, faithful to reference quirk)
// ---------------------------------------------------------------------------
__global__ void final_kernel(const float* __restrict__ Wlin,
                             const float* __restrict__ blin,
                             float* __restrict__ out)
{
    int idx = threadIdx.x;
    if (idx < TT * 10) {
        int t = idx / 10, o = idx % 10;
        const float* h = &g_hs[0][((size_t)t * BB + (BB - 1)) * HH];
        float s = blin[o];
#pragma unroll
        for (int k = 0; k < HH; ++k) s += h[k] * Wlin[o * HH + k];
        out[idx] = s;
    }
}

// ---------------------------------------------------------------------------
extern "C" void kernel_launch(void* const* d_in, const int* in_sizes, int n_in,
                              void* d_out, int out_size)
{
    const float* x    = (const float*)d_in[0];
    const float* Wih0 = (const float*)d_in[1];
    const float* Whh0 = (const float*)d_in[2];
    const float* bih0 = (const float*)d_in[3];
    const float* bhh0 = (const float*)d_in[4];
    const float* WihR = (const float*)d_in[5];
    const float* WhhR = (const float*)d_in[6];
    const float* bihR = (const float*)d_in[7];
    const float* bhhR = (const float*)d_in[8];
    const float* Wlin = (const float*)d_in[9];
    const float* blin = (const float*)d_in[10];

    float* out = (float*)d_out;
    float* hn  = out + TT * 10;
    float* cn  = hn + (size_t)NL * BB * HH;

    const int SH_P  = 65536 + 66560 + RPP * 64 * 4;       // 148480 B
    const int SH_L0 = 65536 + 32 * 64 * 4;                // 73728 B
    const int SH_HL = 131072 + 16384 + 32768;             // 180224 B

    cudaFuncSetAttribute(proj0_kernel,  cudaFuncAttributeMaxDynamicSharedMemorySize, SH_P);
    cudaFuncSetAttribute(layer0_kernel, cudaFuncAttributeMaxDynamicSharedMemorySize, SH_L0);
    cudaFuncSetAttribute(layer_kernel,  cudaFuncAttributeMaxDynamicSharedMemorySize, SH_HL);

    proj0_kernel<<<(TT * BB) / RPP, NTHR, SH_P>>>(x, Wih0, bih0, bhh0);
    layer0_kernel<<<BB / 32, NTHR, SH_L0>>>(Whh0, hn, cn);

    for (int l = 1; l < NL; ++l) {
        int lr = l - 1;
        layer_kernel<<<BB / 32, 512, SH_HL>>>(
            WihR + (size_t)lr * GG * HH, WhhR + (size_t)lr * GG * HH,
            bihR + lr * GG, bhhR + lr * GG,
            (l - 1) & 1, l & 1,
            hn + (size_t)l * BB * HH, cn + (size_t)l * BB * HH);
    }

    final_kernel<<<1, 256>>>(Wlin, blin, out);
}

// round 7
// speedup vs baseline: 1.2671x; 1.0519x over previous
#include <cuda_runtime.h>

#define TT 25
#define BB 4096
#define INP 500
#define HH 64
#define GG 256   // 4*H
#define NL 25
#define NTHR 256

typedef unsigned long long ull;

// scratch (sanctioned: __device__ globals)
// g_xp0 packed-pair layout: [row][p*32+lane] = (gate lane+64p, gate lane+64p+32)
__device__ ull   g_xp0[(size_t)TT * BB * 128];
__device__ float g_hs[2][(size_t)TT * BB * HH];

__device__ __forceinline__ ull ffma2(ull a, ull b, ull c) {
    ull d; asm("fma.rn.f32x2 %0, %1, %2, %3;" : "=l"(d) : "l"(a), "l"(b), "l"(c)); return d;
}
__device__ __forceinline__ ull add2(ull a, ull b) {
    ull d; asm("add.rn.f32x2 %0, %1, %2;" : "=l"(d) : "l"(a), "l"(b)); return d;
}
__device__ __forceinline__ ull pack2(float x, float y) {
    ull d; asm("mov.b64 %0, {%1, %2};" : "=l"(d) : "f"(x), "f"(y)); return d;
}
__device__ __forceinline__ float2 unpack2(ull v) {
    float2 r; asm("mov.b64 {%0, %1}, %2;" : "=f"(r.x), "=f"(r.y) : "l"(v)); return r;
}
__device__ __forceinline__ float sigf(float x) {
    return __fdividef(1.0f, 1.0f + __expf(-x));
}
__device__ __forceinline__ float tanhf_fast(float x) {
    return 1.0f - __fdividef(2.0f, __expf(2.0f * x) + 1.0f);
}
__device__ __forceinline__ void barpair(int id) {
    asm volatile("bar.sync %0, 64;" :: "r"(id) : "memory");
}

// shared weight layout (ull): slot [(k*4+p)*32 + lane] = (W[lane+64p][k], W[lane+64p+32][k])

// ---------------------------------------------------------------------------
// Layer-0 input projection -> g_xp0 (packed pairs), bias folded in.
// ---------------------------------------------------------------------------
#define RPP 64
__global__ void __launch_bounds__(NTHR)
proj0_kernel(const float* __restrict__ x, const float* __restrict__ W,
             const float* __restrict__ bih, const float* __restrict__ bhh)
{
    extern __shared__ unsigned char smraw[];
    ull*   shW     = (ull*)smraw;                        // 64*4*32 ull = 64 KB
    float* scratch = (float*)(smraw + 65536);            // [256][65] = 66560 B
    float* shX     = (float*)(smraw + 65536 + 66560);    // [64][64]  = 16 KB
    const int tid = threadIdx.x, lane = tid & 31, w = tid >> 5;
    const int rowBase = blockIdx.x * RPP;

    ull acc[8][4];
#pragma unroll
    for (int p = 0; p < 4; ++p) {
        int g0 = lane + 64 * p, g1 = g0 + 32;
        ull b = pack2(bih[g0] + bhh[g0], bih[g1] + bhh[g1]);
#pragma unroll
        for (int r = 0; r < 8; ++r) acc[r][p] = b;
    }

    for (int k0 = 0; k0 < INP; k0 += 64) {
        for (int idx = tid; idx < 64 * GG; idx += NTHR) {
            int kk = idx & 63, g = idx >> 6;
            scratch[g * 65 + kk] = (k0 + kk < INP) ? W[(size_t)g * INP + k0 + kk] : 0.0f;
        }
        for (int idx = tid; idx < RPP * 64; idx += NTHR) {
            int kk = idx & 63, r = idx >> 6;
            shX[r * 64 + kk] = (k0 + kk < INP) ? x[(size_t)(rowBase + r) * INP + k0 + kk] : 0.0f;
        }
        __syncthreads();
        for (int idx = tid; idx < 64 * 128; idx += NTHR) {
            int l2 = idx & 31, p = (idx >> 5) & 3, kk = idx >> 7;
            int g0 = 64 * p + l2;
            shW[(kk * 4 + p) * 32 + l2] = pack2(scratch[g0 * 65 + kk], scratch[(g0 + 32) * 65 + kk]);
        }
        __syncthreads();
#pragma unroll 2
        for (int k4 = 0; k4 < 64; k4 += 4) {
            float4 xq[8];
#pragma unroll
            for (int r = 0; r < 8; ++r) xq[r] = *(const float4*)&shX[(8 * w + r) * 64 + k4];
#pragma unroll
            for (int kk = 0; kk < 4; ++kk) {
                ull wv[4];
#pragma unroll
                for (int p = 0; p < 4; ++p) wv[p] = shW[((k4 + kk) * 4 + p) * 32 + lane];
#pragma unroll
                for (int r = 0; r < 8; ++r) {
                    float xv = ((const float*)&xq[r])[kk];
                    ull xx = pack2(xv, xv);
#pragma unroll
                    for (int p = 0; p < 4; ++p) acc[r][p] = ffma2(xx, wv[p], acc[r][p]);
                }
            }
        }
        __syncthreads();
    }
#pragma unroll
    for (int r = 0; r < 8; ++r) {
        size_t rb = (size_t)(rowBase + 8 * w + r) * 128;
#pragma unroll
        for (int p = 0; p < 4; ++p) g_xp0[rb + p * 32 + lane] = acc[r][p];
    }
}

// ---------------------------------------------------------------------------
// Layer 0 recurrence (K=64): gates = xp0[t] + h @ Whh^T. 32 rows/block.
// ---------------------------------------------------------------------------
__global__ void __launch_bounds__(NTHR)
layer0_kernel(const float* __restrict__ Whh,
              float* __restrict__ out_hn, float* __restrict__ out_cn)
{
    extern __shared__ unsigned char smraw[];
    ull*   shW  = (ull*)smraw;                 // 64*4*32 ull
    float* shWf = (float*)shW;
    float* shH  = (float*)(smraw + 65536);     // [32][64]
    const int tid = threadIdx.x, lane = tid & 31, w = tid >> 5;
    const int rowBase = blockIdx.x * 32;

    for (int idx = tid; idx < 64 * GG; idx += NTHR) {
        int g = idx & 255, kk = idx >> 8;
        int p = g >> 6, half = (g >> 5) & 1, l2 = g & 31;
        shWf[((kk * 4 + p) * 32 + l2) * 2 + half] = Whh[g * HH + kk];
    }
    for (int idx = tid; idx < 32 * HH; idx += NTHR) shH[idx] = 0.0f;
    __syncthreads();

    float c0[4] = {0, 0, 0, 0}, c1[4] = {0, 0, 0, 0};

    for (int t = 0; t < TT; ++t) {
        ull acc[4][4];
#pragma unroll
        for (int r = 0; r < 4; ++r) {
            size_t base = ((size_t)t * BB + rowBase + 4 * w + r) * 128;
#pragma unroll
            for (int p = 0; p < 4; ++p) acc[r][p] = g_xp0[base + p * 32 + lane];
        }
#pragma unroll 4
        for (int k4 = 0; k4 < 64; k4 += 4) {
            float4 xq[4];
#pragma unroll
            for (int r = 0; r < 4; ++r) xq[r] = *(const float4*)&shH[(4 * w + r) * 64 + k4];
#pragma unroll
            for (int kk = 0; kk < 4; ++kk) {
                ull wv[4];
#pragma unroll
                for (int p = 0; p < 4; ++p) wv[p] = shW[((k4 + kk) * 4 + p) * 32 + lane];
#pragma unroll
                for (int r = 0; r < 4; ++r) {
                    float xv = ((const float*)&xq[r])[kk];
                    ull xx = pack2(xv, xv);
#pragma unroll
                    for (int p = 0; p < 4; ++p) acc[r][p] = ffma2(xx, wv[p], acc[r][p]);
                }
            }
        }
        __syncwarp();
#pragma unroll
        for (int r = 0; r < 4; ++r) {
            float2 fi = unpack2(acc[r][0]), ff = unpack2(acc[r][1]);
            float2 fq = unpack2(acc[r][2]), fo = unpack2(acc[r][3]);
            float i0 = sigf(fi.x), i1 = sigf(fi.y);
            float f0 = sigf(ff.x), f1 = sigf(ff.y);
            float q0 = tanhf_fast(fq.x), q1 = tanhf_fast(fq.y);
            float o0 = sigf(fo.x), o1 = sigf(fo.y);
            c0[r] = f0 * c0[r] + i0 * q0;
            c1[r] = f1 * c1[r] + i1 * q1;
            float h0 = o0 * tanhf_fast(c0[r]);
            float h1 = o1 * tanhf_fast(c1[r]);
            shH[(4 * w + r) * 64 + lane]      = h0;
            shH[(4 * w + r) * 64 + lane + 32] = h1;
            size_t ob = ((size_t)t * BB + rowBase + 4 * w + r) * HH;
            g_hs[0][ob + lane]      = h0;
            g_hs[0][ob + lane + 32] = h1;
            if (t == TT - 1) {
                size_t hb = (size_t)(rowBase + 4 * w + r) * HH;
                out_hn[hb + lane] = h0;      out_hn[hb + lane + 32] = h1;
                out_cn[hb + lane] = c0[r];   out_cn[hb + lane + 32] = c1[r];
            }
        }
        __syncwarp();
    }
}

// ---------------------------------------------------------------------------
// Hidden layer l>=1 (K=128), 256 threads / 8 warps, x/h warp specialization:
//   warps 0-3 (x-role, rg=w):   k 0..63 from hs_in; runs 1 step ahead
//   warps 4-7 (h-role, rg=w-4): k 64..127 from own h; reduction+elementwise
// Pair (x_rg, h_rg) shares SMSP rg; syncs via named barrier rg+1 (64 thr).
// ---------------------------------------------------------------------------
// smem: shW 131072 | redX 65536 | shX 16384 | shH 8192  = 221184 B
__global__ void __launch_bounds__(NTHR)
layer_kernel(const float* __restrict__ Wih, const float* __restrict__ Whh,
             const float* __restrict__ bih, const float* __restrict__ bhh,
             int inSel, int outSel,
             float* __restrict__ out_hn, float* __restrict__ out_cn)
{
    extern __shared__ unsigned char smraw[];
    ull*   shW  = (ull*)smraw;                       // [(k*4+p)*32+lane], k 0..127
    float* shWf = (float*)shW;
    ull*   red  = (ull*)(smraw + 131072);            // [rg][buf][r*4+p][lane]
    float* shX  = (float*)(smraw + 131072 + 65536);  // [rg][buf][8][64]
    float* shH  = (float*)(smraw + 131072 + 65536 + 16384); // [rg][8][64]
    const int tid = threadIdx.x, lane = tid & 31, w = tid >> 5;
    const int isH = w >> 2, rg = w & 3;
    const int rowBase = blockIdx.x * 32 + rg * 8;    // this pair's 8 rows
    const float* __restrict__ hs_in  = g_hs[inSel];
    float* __restrict__       hs_out = g_hs[outSel];

    // stage both weight halves (all warps), g-fast: 2-way STS conflicts only
    for (int idx = tid; idx < 64 * GG; idx += NTHR) {
        int g = idx & 255, kk = idx >> 8;
        int p = g >> 6, half = (g >> 5) & 1, l2 = g & 31;
        shWf[((kk * 4 + p) * 32 + l2) * 2 + half]        = Wih[g * HH + kk];
        shWf[(((64 + kk) * 4 + p) * 32 + l2) * 2 + half] = Whh[g * HH + kk];
    }
    __syncthreads();

    // lane -> (row, k) mapping for x staging: 4 passes of 2 rows each
    const int srow = lane >> 4;          // 0..1
    const int skb  = (lane & 15) * 4;    // 0..60

    if (!isH) {
        // ================= x-role warp =================
        ull bsum[4];
#pragma unroll
        for (int p = 0; p < 4; ++p) {
            int g0 = lane + 64 * p, g1 = g0 + 32;
            bsum[p] = pack2(bih[g0] + bhh[g0], bih[g1] + bhh[g1]);
        }
        // stage x(t=0) into buf 0
        float* x0 = &shX[(rg * 2 + 0) * 8 * 64];
#pragma unroll
        for (int pz = 0; pz < 4; ++pz) {
            int r = 2 * pz + srow;
            float4 v = *(const float4*)&hs_in[((size_t)0 * BB + rowBase + r) * HH + skb];
            *(float4*)&x0[r * 64 + skb] = v;
        }
        __syncwarp();

        for (int t = 0; t < TT; ++t) {
            // prefetch x(t+1) into regs (hidden under FFMA below)
            float4 pf[4];
            if (t + 1 < TT) {
#pragma unroll
                for (int pz = 0; pz < 4; ++pz) {
                    int r = 2 * pz + srow;
                    pf[pz] = *(const float4*)&hs_in[((size_t)(t + 1) * BB + rowBase + r) * HH + skb];
                }
            }
            const float* xb = &shX[(rg * 2 + (t & 1)) * 8 * 64];
            ull acc[8][4];
#pragma unroll
            for (int r = 0; r < 8; ++r)
#pragma unroll
                for (int p = 0; p < 4; ++p) acc[r][p] = bsum[p];
#pragma unroll 2
            for (int k4 = 0; k4 < 64; k4 += 4) {
                float4 xq[8];
#pragma unroll
                for (int r = 0; r < 8; ++r) xq[r] = *(const float4*)&xb[r * 64 + k4];
#pragma unroll
                for (int kk = 0; kk < 4; ++kk) {
                    ull wv[4];
#pragma unroll
                    for (int p = 0; p < 4; ++p) wv[p] = shW[((k4 + kk) * 4 + p) * 32 + lane];
#pragma unroll
                    for (int r = 0; r < 8; ++r) {
                        float xv = ((const float*)&xq[r])[kk];
                        ull xx = pack2(xv, xv);
#pragma unroll
                        for (int p = 0; p < 4; ++p) acc[r][p] = ffma2(xx, wv[p], acc[r][p]);
                    }
                }
            }
            // publish partial (double-buffered)
            ull* rb = &red[((rg * 2 + (t & 1)) * 32) * 32];
#pragma unroll
            for (int r = 0; r < 8; ++r)
#pragma unroll
                for (int p = 0; p < 4; ++p) rb[(r * 4 + p) * 32 + lane] = acc[r][p];
            // stage x(t+1)
            if (t + 1 < TT) {
                float* xn = &shX[(rg * 2 + ((t + 1) & 1)) * 8 * 64];
#pragma unroll
                for (int pz = 0; pz < 4; ++pz) {
                    int r = 2 * pz + srow;
                    *(float4*)&xn[r * 64 + skb] = pf[pz];
                }
            }
            __syncwarp();
            barpair(rg + 1);
        }
    } else {
        // ================= h-role warp =================
        float c0[8], c1[8];
#pragma unroll
        for (int r = 0; r < 8; ++r) { c0[r] = 0.0f; c1[r] = 0.0f; }
        float* hb = &shH[rg * 8 * 64];

        for (int t = 0; t < TT; ++t) {
            ull acc[8][4];
#pragma unroll
            for (int r = 0; r < 8; ++r)
#pragma unroll
                for (int p = 0; p < 4; ++p) acc[r][p] = 0ULL;
            if (t > 0) {
#pragma unroll 2
                for (int k4 = 0; k4 < 64; k4 += 4) {
                    float4 xq[8];
#pragma unroll
                    for (int r = 0; r < 8; ++r) xq[r] = *(const float4*)&hb[r * 64 + k4];
#pragma unroll
                    for (int kk = 0; kk < 4; ++kk) {
                        ull wv[4];
#pragma unroll
                        for (int p = 0; p < 4; ++p)
                            wv[p] = shW[((64 + k4 + kk) * 4 + p) * 32 + lane];
#pragma unroll
                        for (int r = 0; r < 8; ++r) {
                            float xv = ((const float*)&xq[r])[kk];
                            ull xx = pack2(xv, xv);
#pragma unroll
                            for (int p = 0; p < 4; ++p) acc[r][p] = ffma2(xx, wv[p], acc[r][p]);
                        }
                    }
                }
            }
            barpair(rg + 1);   // x partial for t is now published
            const ull* rb = &red[((rg * 2 + (t & 1)) * 32) * 32];
#pragma unroll
            for (int r = 0; r < 8; ++r) {
#pragma unroll
                for (int p = 0; p < 4; ++p)
                    acc[r][p] = add2(acc[r][p], rb[(r * 4 + p) * 32 + lane]);
                float2 fi = unpack2(acc[r][0]), ff = unpack2(acc[r][1]);
                float2 fq = unpack2(acc[r][2]), fo = unpack2(acc[r][3]);
                float i0 = sigf(fi.x), i1 = sigf(fi.y);
                float f0 = sigf(ff.x), f1 = sigf(ff.y);
                float q0 = tanhf_fast(fq.x), q1 = tanhf_fast(fq.y);
                float o0 = sigf(fo.x), o1 = sigf(fo.y);
                c0[r] = f0 * c0[r] + i0 * q0;
                c1[r] = f1 * c1[r] + i1 * q1;
                float h0 = o0 * tanhf_fast(c0[r]);
                float h1 = o1 * tanhf_fast(c1[r]);
                hb[r * 64 + lane]      = h0;
                hb[r * 64 + lane + 32] = h1;
                size_t ob = ((size_t)t * BB + rowBase + r) * HH;
                hs_out[ob + lane]      = h0;
                hs_out[ob + lane + 32] = h1;
                if (t == TT - 1) {
                    size_t hbg = (size_t)(rowBase + r) * HH;
                    out_hn[hbg + lane] = h0;      out_hn[hbg + lane + 32] = h1;
                    out_cn[hbg + lane] = c0[r];   out_cn[hbg + lane + 32] = c1[r];
                }
            }
            __syncwarp();   // h visible to whole warp before next-t LDS
        }
    }
}

// ---------------------------------------------------------------------------
// Final linear on hs[:, -1, :] (batch index B-1, faithful to reference quirk)
// ---------------------------------------------------------------------------
__global__ void final_kernel(const float* __restrict__ Wlin,
                             const float* __restrict__ blin,
                             float* __restrict__ out)
{
    int idx = threadIdx.x;
    if (idx < TT * 10) {
        int t = idx / 10, o = idx % 10;
        const float* h = &g_hs[0][((size_t)t * BB + (BB - 1)) * HH];
        float s = blin[o];
#pragma unroll
        for (int k = 0; k < HH; ++k) s += h[k] * Wlin[o * HH + k];
        out[idx] = s;
    }
}

// ---------------------------------------------------------------------------
extern "C" void kernel_launch(void* const* d_in, const int* in_sizes, int n_in,
                              void* d_out, int out_size)
{
    const float* x    = (const float*)d_in[0];
    const float* Wih0 = (const float*)d_in[1];
    const float* Whh0 = (const float*)d_in[2];
    const float* bih0 = (const float*)d_in[3];
    const float* bhh0 = (const float*)d_in[4];
    const float* WihR = (const float*)d_in[5];
    const float* WhhR = (const float*)d_in[6];
    const float* bihR = (const float*)d_in[7];
    const float* bhhR = (const float*)d_in[8];
    const float* Wlin = (const float*)d_in[9];
    const float* blin = (const float*)d_in[10];

    float* out = (float*)d_out;
    float* hn  = out + TT * 10;
    float* cn  = hn + (size_t)NL * BB * HH;

    const int SH_P  = 65536 + 66560 + RPP * 64 * 4;       // 148480 B
    const int SH_L0 = 65536 + 32 * 64 * 4;                // 73728 B
    const int SH_HL = 131072 + 65536 + 16384 + 8192;      // 221184 B

    cudaFuncSetAttribute(proj0_kernel,  cudaFuncAttributeMaxDynamicSharedMemorySize, SH_P);
    cudaFuncSetAttribute(layer0_kernel, cudaFuncAttributeMaxDynamicSharedMemorySize, SH_L0);
    cudaFuncSetAttribute(layer_kernel,  cudaFuncAttributeMaxDynamicSharedMemorySize, SH_HL);

    proj0_kernel<<<(TT * BB) / RPP, NTHR, SH_P>>>(x, Wih0, bih0, bhh0);
    layer0_kernel<<<BB / 32, NTHR, SH_L0>>>(Whh0, hn, cn);

    for (int l = 1; l < NL; ++l) {
        int lr = l - 1;
        layer_kernel<<<BB / 32, NTHR, SH_HL>>>(
            WihR + (size_t)lr * GG * HH, WhhR + (size_t)lr * GG * HH,
            bihR + lr * GG, bhhR + lr * GG,
            (l - 1) & 1, l & 1,
            hn + (size_t)l * BB * HH, cn + (size_t)l * BB * HH);
    }

    final_kernel<<<1, 256>>>(Wlin, blin, out);
}